// round 9
// baseline (speedup 1.0000x reference)
#include <cuda_runtime.h>
#include <cuda_bf16.h>

#define Bsz   256
#define Tsz   512
#define Tpad  520
#define Csz   128
#define Lsz   64
#define BLANKC 127
#define PF    4
#define LN2f  0.69314718055994530942f
#define ESENT (-(1 << 29))

// g_pk[b][t][lane] = bf16x2(p_label(2*lane), p_label(2*lane+1)); g_pb = blank prob (f32)
__device__ unsigned int g_pk[(size_t)Bsz * Tpad * 32];
__device__ float        g_pb[(size_t)Bsz * Tpad];

// ---------------------------------------------------------------------------
// Kernel 1: softmax per (b,t) row; gather label probs (bf16x2) + blank (f32).
// One warp per row, 4 rows per 128-thread block.
// ---------------------------------------------------------------------------
__global__ __launch_bounds__(128)
void ctc_probs(const float* __restrict__ y_pred,
               const int*   __restrict__ y_true) {
    const int row  = blockIdx.x * 4 + (threadIdx.x >> 5);   // row = b*512 + t
    const int lane = threadIdx.x & 31;
    const int wid  = (threadIdx.x >> 5);

    __shared__ float sh[4][128];

    const float4 v = reinterpret_cast<const float4*>(y_pred + (size_t)row * Csz)[lane];
    float m = fmaxf(fmaxf(v.x, v.y), fmaxf(v.z, v.w));
    #pragma unroll
    for (int o = 16; o; o >>= 1) m = fmaxf(m, __shfl_xor_sync(0xffffffffu, m, o));

    const float ex = __expf(v.x - m), ey = __expf(v.y - m),
                ez = __expf(v.z - m), ew = __expf(v.w - m);
    float esum = (ex + ey) + (ez + ew);
    #pragma unroll
    for (int o = 16; o; o >>= 1) esum += __shfl_xor_sync(0xffffffffu, esum, o);
    const float inv = __frcp_rn(esum);

    reinterpret_cast<float4*>(sh[wid])[lane] = make_float4(ex, ey, ez, ew);
    __syncwarp();

    const int b = row >> 9;
    const int t = row & 511;
    const int* yt = y_true + b * Lsz;
    const float p1 = sh[wid][yt[2 * lane]]     * inv;
    const float p3 = sh[wid][yt[2 * lane + 1]] * inv;

    const __nv_bfloat162 pk = __floats2bfloat162_rn(p1, p3);  // .x in low half
    g_pk[((size_t)b * Tpad + t) * 32 + lane] =
        *reinterpret_cast<const unsigned int*>(&pk);
    if (lane == 0) g_pb[(size_t)b * Tpad + t] = sh[wid][BLANKC] * inv;
}

// exponent-injection: m * 2^d with clamp; m normalized in [1,2)
__device__ __forceinline__ float inj(float m, int d) {
    return __int_as_float(__float_as_int(m) + (max(d, -100) << 23));
}
// renormalize v (>0) carrying exponent E -> mant in [1,2), int exp
__device__ __forceinline__ void norm2(float v, int E, float& m, int& e) {
    const int vb = __float_as_int(v);
    m = __int_as_float((vb & 0x007FFFFF) | 0x3F800000);
    e = E + (vb >> 23) - 127;
}

// ---------------------------------------------------------------------------
// Kernel 2: warp-per-row alpha recurrence, 4 rows per CTA (one warp/SMSP).
// REMAP: lane l owns states 4l+1..4l+4 (all useful; covers 1..128).
// State 0 (pure blank self-chain) is a warp-uniform scalar: a0 *= pb.
// Cross-lane per step: prev lane's states 4l (m4) and 4l-1 (m3) -> 4 shfl.
// Alignment by exponent injection (no weight builds, no extra FMUL).
// ---------------------------------------------------------------------------
__global__ __launch_bounds__(128)
void ctc_alpha(const int* __restrict__ y_true,
               const int* __restrict__ input_length,
               const int* __restrict__ label_length,
               float*     __restrict__ out) {
    const int b   = blockIdx.x * 4 + (threadIdx.x >> 5);
    const int l   = threadIdx.x & 31;
    const int wid = threadIdx.x >> 5;

    const int z_lo = y_true[b * Lsz + 2 * l];          // label of state 4l+1
    const int z_hi = y_true[b * Lsz + 2 * l + 1];      // label of state 4l+3
    const bool skip1 = (l > 0) &&
                       (z_lo != y_true[b * Lsz + max(2 * l - 1, 0)]);
    const bool skip3 = (z_hi != z_lo);
    const int T_run = input_length[b];

    const unsigned int* pk  = g_pk + (size_t)b * Tpad * 32 + l;  // stride 32/t
    const float*        pbp = g_pb + (size_t)b * Tpad;

    // states: m in [1,2), e int exponent; phantom = (1.0f, ESENT)
    float m1 = 1.f, m2 = 1.f, m3 = 1.f, m4 = 1.f, mz;
    int   e1 = ESENT, e2 = ESENT, e3 = ESENT, e4 = ESENT, ez;

    {   // t = 0 init
        norm2(pbp[0], 0, mz, ez);                      // state 0 = pb(0)
        if (l == 0) {                                  // state 1 = p_label0(0)
            const unsigned int u0 = pk[0];
            norm2(__int_as_float(u0 << 16), 0, m1, e1);
        }
    }

    // prefetch ring t = 1..PF
    unsigned int xr[PF]; float pr[PF];
    #pragma unroll
    for (int i = 0; i < PF; ++i) {
        xr[i] = pk[(size_t)(1 + i) * 32];
        pr[i] = pbp[1 + i];
    }

#define STEP(tc, j) {                                                         \
    const unsigned int u = xr[j];                                             \
    const float pbv = pr[j];                                                  \
    xr[j] = pk[(size_t)((tc) + PF) * 32];                                     \
    pr[j] = pbp[(tc) + PF];                                                   \
    const float p1v = __int_as_float(u << 16);                                \
    const float p3v = __int_as_float(u & 0xFFFF0000u);                        \
    float mP4 = __shfl_up_sync(0xffffffffu, m4, 1);                           \
    int   eP4 = __shfl_up_sync(0xffffffffu, e4, 1);                           \
    const float mP3 = __shfl_up_sync(0xffffffffu, m3, 1);                     \
    int   eP3 = __shfl_up_sync(0xffffffffu, e3, 1);                           \
    if (l == 0) { mP4 = mz; eP4 = ez; eP3 = ESENT; }                          \
    float nm1, nm2, nm3, nm4; int ne1, ne2, ne3, ne4;                         \
    { const int eS = skip1 ? eP3 : ESENT;                                     \
      const int E  = max(e1, max(eP4, eS));                                   \
      const float v = (inj(m1, e1 - E) + inj(mP4, eP4 - E)                    \
                       + inj(mP3, eS - E)) * p1v;                             \
      norm2(v, E, nm1, ne1); }                                                \
    { const int E = max(e2, e1);                                              \
      const float v = (inj(m2, e2 - E) + inj(m1, e1 - E)) * pbv;              \
      norm2(v, E, nm2, ne2); }                                                \
    { const int eS = skip3 ? e1 : ESENT;                                      \
      const int E  = max(e3, max(e2, eS));                                    \
      const float v = (inj(m3, e3 - E) + inj(m2, e2 - E)                      \
                       + inj(m1, eS - E)) * p3v;                              \
      norm2(v, E, nm3, ne3); }                                                \
    { const int E = max(e4, e3);                                              \
      const float v = (inj(m4, e4 - E) + inj(m3, e3 - E)) * pbv;              \
      norm2(v, E, nm4, ne4); }                                                \
    { const float v = mz * pbv; norm2(v, ez, mz, ez); }                       \
    m1 = nm1; e1 = ne1; m2 = nm2; e2 = ne2;                                   \
    m3 = nm3; e3 = ne3; m4 = nm4; e4 = ne4; }

    const int nsteps = T_run - 1;       // steps t = 1 .. T_run-1
    const int nfull  = nsteps >> 2;     // PF = 4
    const int rem    = nsteps & 3;

    int t = 1;
    for (int c = 0; c < nfull; ++c) {   // branch-free steady state
        #pragma unroll
        for (int j = 0; j < PF; ++j) STEP(t + j, j)
        t += PF;
    }
    #pragma unroll
    for (int j = 0; j < PF; ++j) {      // epilogue: warp-uniform guards
        if (j < rem) STEP(t + j, j)
    }
#undef STEP

    // stage states 1..128 for readout
    __shared__ float2 sh[4][132];
    sh[wid][4 * l + 1] = make_float2(m1, __int_as_float(e1));
    sh[wid][4 * l + 2] = make_float2(m2, __int_as_float(e2));
    sh[wid][4 * l + 3] = make_float2(m3, __int_as_float(e3));
    sh[wid][4 * l + 4] = make_float2(m4, __int_as_float(e4));
    __syncwarp();

    if (l == 0) {
        const int ll = label_length[b];
        const float2 u = sh[wid][2 * ll];
        const float2 v = sh[wid][2 * ll - 1];
        const int eu = __float_as_int(u.y);
        const int ev = __float_as_int(v.y);
        const int Em = max(eu, ev);
        const float sum = inj(u.x, eu - Em) + inj(v.x, ev - Em);
        out[b] = -(__logf(sum) + (float)Em * LN2f);
    }
}

// ---------------------------------------------------------------------------
extern "C" void kernel_launch(void* const* d_in, const int* in_sizes, int n_in,
                              void* d_out, int out_size) {
    const int*   y_true = nullptr;
    const float* y_pred = nullptr;
    const int*   ilen   = nullptr;
    const int*   llen   = nullptr;
    for (int i = 0; i < n_in; ++i) {
        const int sz = in_sizes[i];
        if (sz == Bsz * Tsz * Csz)      y_pred = (const float*)d_in[i];
        else if (sz == Bsz * Lsz)       y_true = (const int*)d_in[i];
        else if (sz == Bsz) {
            if (!ilen) ilen = (const int*)d_in[i];
            else       llen = (const int*)d_in[i];
        }
    }
    float* out = (float*)d_out;

    ctc_probs<<<(Bsz * Tsz) / 4, 128>>>(y_pred, y_true);
    ctc_alpha<<<Bsz / 4, 128>>>(y_true, ilen, llen, out);
}